// round 1
// baseline (speedup 1.0000x reference)
#include <cuda_runtime.h>

// EM_rec_loss: fused single-pass loss on GB300.
//
// Inputs (metadata order):
//   d_in[0] segmentations   [8,4,7,128,128]   f32
//   d_in[1] masks           [8,4,7,128,128]   f32
//   d_in[2] reconstructions [8,4,7,3,128,128] f32
//   d_in[3] rec_tgt         [8,4,3,128,128]   f32
//   d_in[4] masks_vis       [8,4,7,128,128]   f32
//   d_in[5] attn_index      [8,4,7,7]         f32
// Output: scalar f32.

#define NB 7
#define NS 7
#define HH 128
#define WW 128
#define HW (HH * WW)        // 16384
#define HW4 (HW / 4)        // 4096 float4 groups per image plane
#define NIMG 32             // b*f
#define TPB 256
#define BPN (HW4 / TPB)     // 16 blocks per image
#define GRID (NIMG * BPN)   // 512 blocks

__device__ float g_part[GRID];

__global__ __launch_bounds__(TPB) void loss_main(
    const float* __restrict__ seg,
    const float* __restrict__ masks,
    const float* __restrict__ rec,
    const float* __restrict__ tgt,
    const float* __restrict__ mvis,
    const float* __restrict__ ai)
{
    __shared__ float s_aib[NS * NB];  // ai * (1/HW)  (BCE weight)
    __shared__ float s_aim[NS * NB];  // ai * 0.1     (MSE weight)
    __shared__ float s_asum[NB];      // sum_s ai*(1/HW)

    const int n = blockIdx.x / BPN;
    const int t = threadIdx.x;

    if (t < NS * NB) {
        float a = ai[n * NS * NB + t];
        s_aib[t] = a * (1.0f / (float)HW);
        s_aim[t] = a * 0.1f;
    }
    __syncthreads();
    if (t < NB) {
        float s = 0.0f;
        #pragma unroll
        for (int j = 0; j < NS; j++) s += s_aib[j * NB + t];
        s_asum[t] = s;
    }
    __syncthreads();

    const int p4 = (blockIdx.x % BPN) * TPB + t;  // float4 index within one plane

    const float4* __restrict__ seg4 = (const float4*)seg;
    const float4* __restrict__ mk4  = (const float4*)masks;
    const float4* __restrict__ rc4  = (const float4*)rec;
    const float4* __restrict__ tg4  = (const float4*)tgt;
    const float4* __restrict__ mv4  = (const float4*)mvis;

    // Per-pixel-component mask weights: wm[b][c], wmv[b][c]
    float wm[NB][4];
    float wmv[NB][4];
    #pragma unroll
    for (int b = 0; b < NB; b++)
        #pragma unroll
        for (int c = 0; c < 4; c++) { wm[b][c] = 0.0f; wmv[b][c] = 0.0f; }

    #pragma unroll
    for (int s = 0; s < NS; s++) {
        float4 mk = mk4[(size_t)(n * NS + s) * HW4 + p4];
        float4 mv = mv4[(size_t)(n * NS + s) * HW4 + p4];
        float mb[4] = { mk.x > 0.5f ? 1.0f : 0.0f, mk.y > 0.5f ? 1.0f : 0.0f,
                        mk.z > 0.5f ? 1.0f : 0.0f, mk.w > 0.5f ? 1.0f : 0.0f };
        float vb[4] = { mv.x > 0.5f ? 1.0f : 0.0f, mv.y > 0.5f ? 1.0f : 0.0f,
                        mv.z > 0.5f ? 1.0f : 0.0f, mv.w > 0.5f ? 1.0f : 0.0f };
        #pragma unroll
        for (int b = 0; b < NB; b++) {
            float ab = s_aib[s * NB + b];
            float am = s_aim[s * NB + b];
            #pragma unroll
            for (int c = 0; c < 4; c++) {
                wm[b][c]  = fmaf(mb[c], ab, wm[b][c]);
                wmv[b][c] = fmaf(vb[c], am, wmv[b][c]);
            }
        }
    }

    // Target pixels (3 channels)
    float4 t0 = tg4[((size_t)n * 3 + 0) * HW4 + p4];
    float4 t1 = tg4[((size_t)n * 3 + 1) * HW4 + p4];
    float4 t2 = tg4[((size_t)n * 3 + 2) * HW4 + p4];
    float tv0[4] = { t0.x, t0.y, t0.z, t0.w };
    float tv1[4] = { t1.x, t1.y, t1.z, t1.w };
    float tv2[4] = { t2.x, t2.y, t2.z, t2.w };

    float acc[4] = { 0.0f, 0.0f, 0.0f, 0.0f };

    #pragma unroll
    for (int b = 0; b < NB; b++) {
        // --- MSE part: e_b = sum_c (rec - tgt)^2, weighted by wmv ---
        float4 r0 = rc4[((size_t)(n * NB + b) * 3 + 0) * HW4 + p4];
        float4 r1 = rc4[((size_t)(n * NB + b) * 3 + 1) * HW4 + p4];
        float4 r2 = rc4[((size_t)(n * NB + b) * 3 + 2) * HW4 + p4];
        float rv0[4] = { r0.x, r0.y, r0.z, r0.w };
        float rv1[4] = { r1.x, r1.y, r1.z, r1.w };
        float rv2[4] = { r2.x, r2.y, r2.z, r2.w };

        // --- BCE part ---
        float4 sg = seg4[(size_t)(n * NB + b) * HW4 + p4];
        float sv[4] = { sg.x, sg.y, sg.z, sg.w };

        float asb = s_asum[b];
        #pragma unroll
        for (int c = 0; c < 4; c++) {
            float d0 = rv0[c] - tv0[c];
            float d1 = rv1[c] - tv1[c];
            float d2 = rv2[c] - tv2[c];
            float e = fmaf(d0, d0, fmaf(d1, d1, d2 * d2));
            acc[c] = fmaf(e, wmv[b][c], acc[c]);

            float lp  = fmaxf(__logf(sv[c]), -100.0f);
            float l1p = fmaxf(__logf(1.0f - sv[c]), -100.0f);
            acc[c] = fmaf(-l1p, asb, acc[c]);
            acc[c] = fmaf(l1p - lp, wm[b][c], acc[c]);
        }
    }

    float total = (acc[0] + acc[1]) + (acc[2] + acc[3]);

    // Deterministic block tree-reduction
    __shared__ float red[TPB];
    red[t] = total;
    __syncthreads();
    #pragma unroll
    for (int off = TPB / 2; off > 0; off >>= 1) {
        if (t < off) red[t] += red[t + off];
        __syncthreads();
    }
    if (t == 0) g_part[blockIdx.x] = red[0];
}

__global__ __launch_bounds__(GRID) void loss_reduce(float* __restrict__ out)
{
    __shared__ float red[GRID];
    int t = threadIdx.x;
    red[t] = g_part[t];
    __syncthreads();
    #pragma unroll
    for (int off = GRID / 2; off > 0; off >>= 1) {
        if (t < off) red[t] += red[t + off];
        __syncthreads();
    }
    if (t == 0) {
        // final scale: LOSS_WEIGHT / (b*f*ns*nb) = 20 / 1568
        out[0] = red[0] * (20.0f / 1568.0f);
    }
}

extern "C" void kernel_launch(void* const* d_in, const int* in_sizes, int n_in,
                              void* d_out, int out_size)
{
    (void)in_sizes; (void)n_in; (void)out_size;
    const float* seg  = (const float*)d_in[0];
    const float* mks  = (const float*)d_in[1];
    const float* rec  = (const float*)d_in[2];
    const float* tgt  = (const float*)d_in[3];
    const float* mvis = (const float*)d_in[4];
    const float* ai   = (const float*)d_in[5];
    float* out = (float*)d_out;

    loss_main<<<GRID, TPB>>>(seg, mks, rec, tgt, mvis, ai);
    loss_reduce<<<1, GRID>>>(out);
}

// round 2
// speedup vs baseline: 1.2000x; 1.2000x over previous
#include <cuda_runtime.h>

// EM_rec_loss: fully fused single-kernel loss on GB300.
//
// Inputs (metadata order):
//   d_in[0] segmentations   [8,4,7,128,128]   f32
//   d_in[1] masks           [8,4,7,128,128]   f32
//   d_in[2] reconstructions [8,4,7,3,128,128] f32
//   d_in[3] rec_tgt         [8,4,3,128,128]   f32
//   d_in[4] masks_vis       [8,4,7,128,128]   f32
//   d_in[5] attn_index      [8,4,7,7]         f32
// Output: scalar f32.

#define NB 7
#define NS 7
#define HH 128
#define WW 128
#define HW (HH * WW)        // 16384
#define HW4 (HW / 4)        // 4096 float4 groups per image plane
#define NIMG 32             // b*f
#define TPB 256
#define BPN (HW4 / TPB)     // 16 blocks per image
#define GRID (NIMG * BPN)   // 512 blocks

__device__ float        g_part[GRID];
__device__ unsigned int g_cnt = 0;   // wraps to 0 every full grid -> graph-replay safe

__global__ __launch_bounds__(TPB) void loss_main(
    const float* __restrict__ seg,
    const float* __restrict__ masks,
    const float* __restrict__ rec,
    const float* __restrict__ tgt,
    const float* __restrict__ mvis,
    const float* __restrict__ ai,
    float* __restrict__ out)
{
    __shared__ float s_aib[NS * NB];  // ai * (1/HW)  (BCE weight)
    __shared__ float s_aim[NS * NB];  // ai * 0.1     (MSE weight)
    __shared__ float s_asum[NB];      // sum_s ai*(1/HW)
    __shared__ float red[TPB];
    __shared__ int   s_last;

    const int n = blockIdx.x / BPN;
    const int t = threadIdx.x;

    if (t < NS * NB) {
        float a = ai[n * NS * NB + t];
        s_aib[t] = a * (1.0f / (float)HW);
        s_aim[t] = a * 0.1f;
    }
    __syncthreads();
    if (t < NB) {
        float s = 0.0f;
        #pragma unroll
        for (int j = 0; j < NS; j++) s += s_aib[j * NB + t];
        s_asum[t] = s;
    }
    __syncthreads();

    const int p4 = (blockIdx.x % BPN) * TPB + t;  // float4 index within one plane

    const float4* __restrict__ seg4 = (const float4*)seg;
    const float4* __restrict__ mk4  = (const float4*)masks;
    const float4* __restrict__ rc4  = (const float4*)rec;
    const float4* __restrict__ tg4  = (const float4*)tgt;
    const float4* __restrict__ mv4  = (const float4*)mvis;

    float acc[4] = { 0.0f, 0.0f, 0.0f, 0.0f };

    // ================= Phase 1: BCE (masks -> wm, then seg logs) =============
    {
        float wm[NB][4];
        #pragma unroll
        for (int b = 0; b < NB; b++)
            #pragma unroll
            for (int c = 0; c < 4; c++) wm[b][c] = 0.0f;

        #pragma unroll
        for (int s = 0; s < NS; s++) {
            float4 mk = mk4[(size_t)(n * NS + s) * HW4 + p4];
            float mb[4] = { mk.x > 0.5f ? 1.0f : 0.0f, mk.y > 0.5f ? 1.0f : 0.0f,
                            mk.z > 0.5f ? 1.0f : 0.0f, mk.w > 0.5f ? 1.0f : 0.0f };
            #pragma unroll
            for (int b = 0; b < NB; b++) {
                float ab = s_aib[s * NB + b];
                #pragma unroll
                for (int c = 0; c < 4; c++)
                    wm[b][c] = fmaf(mb[c], ab, wm[b][c]);
            }
        }

        #pragma unroll
        for (int b = 0; b < NB; b++) {
            float4 sg = seg4[(size_t)(n * NB + b) * HW4 + p4];
            float sv[4] = { sg.x, sg.y, sg.z, sg.w };
            float asb = s_asum[b];
            #pragma unroll
            for (int c = 0; c < 4; c++) {
                float lp  = fmaxf(__logf(sv[c]), -100.0f);
                float l1p = fmaxf(__logf(1.0f - sv[c]), -100.0f);
                acc[c] = fmaf(-l1p, asb, acc[c]);
                acc[c] = fmaf(l1p - lp, wm[b][c], acc[c]);
            }
        }
    }

    // ================= Phase 2: MSE (mvis -> wmv, then rec/tgt) ==============
    {
        float wmv[NB][4];
        #pragma unroll
        for (int b = 0; b < NB; b++)
            #pragma unroll
            for (int c = 0; c < 4; c++) wmv[b][c] = 0.0f;

        #pragma unroll
        for (int s = 0; s < NS; s++) {
            float4 mv = mv4[(size_t)(n * NS + s) * HW4 + p4];
            float vb[4] = { mv.x > 0.5f ? 1.0f : 0.0f, mv.y > 0.5f ? 1.0f : 0.0f,
                            mv.z > 0.5f ? 1.0f : 0.0f, mv.w > 0.5f ? 1.0f : 0.0f };
            #pragma unroll
            for (int b = 0; b < NB; b++) {
                float am = s_aim[s * NB + b];
                #pragma unroll
                for (int c = 0; c < 4; c++)
                    wmv[b][c] = fmaf(vb[c], am, wmv[b][c]);
            }
        }

        float4 t0 = tg4[((size_t)n * 3 + 0) * HW4 + p4];
        float4 t1 = tg4[((size_t)n * 3 + 1) * HW4 + p4];
        float4 t2 = tg4[((size_t)n * 3 + 2) * HW4 + p4];
        float tv0[4] = { t0.x, t0.y, t0.z, t0.w };
        float tv1[4] = { t1.x, t1.y, t1.z, t1.w };
        float tv2[4] = { t2.x, t2.y, t2.z, t2.w };

        #pragma unroll
        for (int b = 0; b < NB; b++) {
            float4 r0 = rc4[((size_t)(n * NB + b) * 3 + 0) * HW4 + p4];
            float4 r1 = rc4[((size_t)(n * NB + b) * 3 + 1) * HW4 + p4];
            float4 r2 = rc4[((size_t)(n * NB + b) * 3 + 2) * HW4 + p4];
            float rv0[4] = { r0.x, r0.y, r0.z, r0.w };
            float rv1[4] = { r1.x, r1.y, r1.z, r1.w };
            float rv2[4] = { r2.x, r2.y, r2.z, r2.w };
            #pragma unroll
            for (int c = 0; c < 4; c++) {
                float d0 = rv0[c] - tv0[c];
                float d1 = rv1[c] - tv1[c];
                float d2 = rv2[c] - tv2[c];
                float e = fmaf(d0, d0, fmaf(d1, d1, d2 * d2));
                acc[c] = fmaf(e, wmv[b][c], acc[c]);
            }
        }
    }

    float total = (acc[0] + acc[1]) + (acc[2] + acc[3]);

    // Deterministic block tree-reduction
    red[t] = total;
    __syncthreads();
    #pragma unroll
    for (int off = TPB / 2; off > 0; off >>= 1) {
        if (t < off) red[t] += red[t + off];
        __syncthreads();
    }

    // Last-block fused final reduction (threadfence-reduction pattern).
    if (t == 0) {
        g_part[blockIdx.x] = red[0];
        __threadfence();
        unsigned int old = atomicInc(&g_cnt, GRID - 1);  // wraps to 0 -> replay-safe
        s_last = (old == GRID - 1) ? 1 : 0;
    }
    __syncthreads();

    if (s_last) {
        // 512 partials, 256 threads: 2 each, then tree. Fixed order -> deterministic.
        float v = g_part[t] + g_part[t + TPB];
        red[t] = v;
        __syncthreads();
        #pragma unroll
        for (int off = TPB / 2; off > 0; off >>= 1) {
            if (t < off) red[t] += red[t + off];
            __syncthreads();
        }
        if (t == 0) {
            // final scale: LOSS_WEIGHT / (b*f*ns*nb) = 20 / 1568
            out[0] = red[0] * (20.0f / 1568.0f);
        }
    }
}

extern "C" void kernel_launch(void* const* d_in, const int* in_sizes, int n_in,
                              void* d_out, int out_size)
{
    (void)in_sizes; (void)n_in; (void)out_size;
    const float* seg  = (const float*)d_in[0];
    const float* mks  = (const float*)d_in[1];
    const float* rec  = (const float*)d_in[2];
    const float* tgt  = (const float*)d_in[3];
    const float* mvis = (const float*)d_in[4];
    const float* ai   = (const float*)d_in[5];
    float* out = (float*)d_out;

    loss_main<<<GRID, TPB>>>(seg, mks, rec, tgt, mvis, ai, out);
}

// round 3
// speedup vs baseline: 1.2490x; 1.0409x over previous
#include <cuda_runtime.h>

// EM_rec_loss: fully fused single-kernel loss on GB300.
//
// Inputs (metadata order):
//   d_in[0] segmentations   [8,4,7,128,128]   f32
//   d_in[1] masks           [8,4,7,128,128]   f32
//   d_in[2] reconstructions [8,4,7,3,128,128] f32
//   d_in[3] rec_tgt         [8,4,3,128,128]   f32
//   d_in[4] masks_vis       [8,4,7,128,128]   f32
//   d_in[5] attn_index      [8,4,7,7]         f32
// Output: scalar f32.

#define NB 7
#define NS 7
#define HH 128
#define WW 128
#define HW (HH * WW)        // 16384
#define HW4 (HW / 4)        // 4096 float4 groups per image plane
#define NIMG 32             // b*f
#define TPB 256
#define NWARP (TPB / 32)    // 8
#define BPN (HW4 / TPB)     // 16 blocks per image
#define GRID (NIMG * BPN)   // 512 blocks

__device__ float        g_part[GRID];
__device__ unsigned int g_cnt = 0;   // wraps to 0 every full grid -> graph-replay safe

__device__ __forceinline__ float warp_sum(float v) {
    // Fixed butterfly order -> deterministic.
    #pragma unroll
    for (int m = 16; m > 0; m >>= 1)
        v += __shfl_xor_sync(0xFFFFFFFFu, v, m);
    return v;
}

__global__ __launch_bounds__(TPB, 4) void loss_main(
    const float* __restrict__ seg,
    const float* __restrict__ masks,
    const float* __restrict__ rec,
    const float* __restrict__ tgt,
    const float* __restrict__ mvis,
    const float* __restrict__ ai,
    float* __restrict__ out)
{
    __shared__ float s_aib[NS * NB];  // ai * (1/HW)  (BCE weight)
    __shared__ float s_aim[NS * NB];  // ai * 0.1     (MSE weight)
    __shared__ float s_asum[NB];      // sum_s ai*(1/HW)
    __shared__ float s_wred[NWARP];
    __shared__ int   s_last;

    const int n = blockIdx.x / BPN;
    const int t = threadIdx.x;

    if (t < NS * NB) {
        float a = ai[n * NS * NB + t];
        s_aib[t] = a * (1.0f / (float)HW);
        s_aim[t] = a * 0.1f;
    }
    __syncthreads();
    if (t < NB) {
        float s = 0.0f;
        #pragma unroll
        for (int j = 0; j < NS; j++) s += s_aib[j * NB + t];
        s_asum[t] = s;
    }
    __syncthreads();

    const int p4 = (blockIdx.x % BPN) * TPB + t;  // float4 index within one plane

    const float4* __restrict__ seg4 = (const float4*)seg;
    const float4* __restrict__ mk4  = (const float4*)masks;
    const float4* __restrict__ rc4  = (const float4*)rec;
    const float4* __restrict__ tg4  = (const float4*)tgt;
    const float4* __restrict__ mv4  = (const float4*)mvis;

    float acc[4] = { 0.0f, 0.0f, 0.0f, 0.0f };

    // ================= Phase 1: BCE (masks -> wm, then seg logs) =============
    {
        float wm[NB][4];
        #pragma unroll
        for (int b = 0; b < NB; b++)
            #pragma unroll
            for (int c = 0; c < 4; c++) wm[b][c] = 0.0f;

        #pragma unroll
        for (int s = 0; s < NS; s++) {
            float4 mk = mk4[(size_t)(n * NS + s) * HW4 + p4];
            float mb[4] = { mk.x > 0.5f ? 1.0f : 0.0f, mk.y > 0.5f ? 1.0f : 0.0f,
                            mk.z > 0.5f ? 1.0f : 0.0f, mk.w > 0.5f ? 1.0f : 0.0f };
            #pragma unroll
            for (int b = 0; b < NB; b++) {
                float ab = s_aib[s * NB + b];
                #pragma unroll
                for (int c = 0; c < 4; c++)
                    wm[b][c] = fmaf(mb[c], ab, wm[b][c]);
            }
        }

        #pragma unroll
        for (int b = 0; b < NB; b++) {
            float4 sg = seg4[(size_t)(n * NB + b) * HW4 + p4];
            float sv[4] = { sg.x, sg.y, sg.z, sg.w };
            float asb = s_asum[b];
            #pragma unroll
            for (int c = 0; c < 4; c++) {
                float lp  = fmaxf(__logf(sv[c]), -100.0f);
                float l1p = fmaxf(__logf(1.0f - sv[c]), -100.0f);
                acc[c] = fmaf(-l1p, asb, acc[c]);
                acc[c] = fmaf(l1p - lp, wm[b][c], acc[c]);
            }
        }
    }

    // ================= Phase 2: MSE (mvis -> wmv, then rec/tgt) ==============
    {
        float wmv[NB][4];
        #pragma unroll
        for (int b = 0; b < NB; b++)
            #pragma unroll
            for (int c = 0; c < 4; c++) wmv[b][c] = 0.0f;

        #pragma unroll
        for (int s = 0; s < NS; s++) {
            float4 mv = mv4[(size_t)(n * NS + s) * HW4 + p4];
            float vb[4] = { mv.x > 0.5f ? 1.0f : 0.0f, mv.y > 0.5f ? 1.0f : 0.0f,
                            mv.z > 0.5f ? 1.0f : 0.0f, mv.w > 0.5f ? 1.0f : 0.0f };
            #pragma unroll
            for (int b = 0; b < NB; b++) {
                float am = s_aim[s * NB + b];
                #pragma unroll
                for (int c = 0; c < 4; c++)
                    wmv[b][c] = fmaf(vb[c], am, wmv[b][c]);
            }
        }

        float4 t0 = tg4[((size_t)n * 3 + 0) * HW4 + p4];
        float4 t1 = tg4[((size_t)n * 3 + 1) * HW4 + p4];
        float4 t2 = tg4[((size_t)n * 3 + 2) * HW4 + p4];
        float tv0[4] = { t0.x, t0.y, t0.z, t0.w };
        float tv1[4] = { t1.x, t1.y, t1.z, t1.w };
        float tv2[4] = { t2.x, t2.y, t2.z, t2.w };

        #pragma unroll
        for (int b = 0; b < NB; b++) {
            float4 r0 = rc4[((size_t)(n * NB + b) * 3 + 0) * HW4 + p4];
            float4 r1 = rc4[((size_t)(n * NB + b) * 3 + 1) * HW4 + p4];
            float4 r2 = rc4[((size_t)(n * NB + b) * 3 + 2) * HW4 + p4];
            float rv0[4] = { r0.x, r0.y, r0.z, r0.w };
            float rv1[4] = { r1.x, r1.y, r1.z, r1.w };
            float rv2[4] = { r2.x, r2.y, r2.z, r2.w };
            #pragma unroll
            for (int c = 0; c < 4; c++) {
                float d0 = rv0[c] - tv0[c];
                float d1 = rv1[c] - tv1[c];
                float d2 = rv2[c] - tv2[c];
                float e = fmaf(d0, d0, fmaf(d1, d1, d2 * d2));
                acc[c] = fmaf(e, wmv[b][c], acc[c]);
            }
        }
    }

    float total = (acc[0] + acc[1]) + (acc[2] + acc[3]);

    // Deterministic block reduction: warp shuffle + tiny smem stage.
    total = warp_sum(total);
    const int lane = t & 31;
    const int warp = t >> 5;
    if (lane == 0) s_wred[warp] = total;
    __syncthreads();
    if (warp == 0) {
        float v = (lane < NWARP) ? s_wred[lane] : 0.0f;
        #pragma unroll
        for (int m = NWARP / 2; m > 0; m >>= 1)
            v += __shfl_xor_sync(0xFFFFFFFFu, v, m);
        if (lane == 0) {
            g_part[blockIdx.x] = v;
            __threadfence();
            unsigned int old = atomicInc(&g_cnt, GRID - 1);  // wraps to 0 -> replay-safe
            s_last = (old == GRID - 1) ? 1 : 0;
        }
    }
    __syncthreads();

    if (s_last) {
        // 512 partials, 256 threads: 2 each, then deterministic tree.
        float v = g_part[t] + g_part[t + TPB];
        v = warp_sum(v);
        if (lane == 0) s_wred[warp] = v;
        __syncthreads();
        if (warp == 0) {
            float u = (lane < NWARP) ? s_wred[lane] : 0.0f;
            #pragma unroll
            for (int m = NWARP / 2; m > 0; m >>= 1)
                u += __shfl_xor_sync(0xFFFFFFFFu, u, m);
            if (lane == 0) {
                // final scale: LOSS_WEIGHT / (b*f*ns*nb) = 20 / 1568
                out[0] = u * (20.0f / 1568.0f);
            }
        }
    }
}

extern "C" void kernel_launch(void* const* d_in, const int* in_sizes, int n_in,
                              void* d_out, int out_size)
{
    (void)in_sizes; (void)n_in; (void)out_size;
    const float* seg  = (const float*)d_in[0];
    const float* mks  = (const float*)d_in[1];
    const float* rec  = (const float*)d_in[2];
    const float* tgt  = (const float*)d_in[3];
    const float* mvis = (const float*)d_in[4];
    const float* ai   = (const float*)d_in[5];
    float* out = (float*)d_out;

    loss_main<<<GRID, TPB>>>(seg, mks, rec, tgt, mvis, ai, out);
}